// round 2
// baseline (speedup 1.0000x reference)
#include <cuda_runtime.h>

#define N_ATOMS 50000
#define N_PAIRS 500000
#define A_IN    75
#define P_IN    14
#define H_A     100
#define H_P     50
#define A_OUT   50
#define P_OUT   50

// Scratch: per-atom projections (allowed as __device__ globals).
__device__ float g_AA[N_ATOMS * H_A];  // relu(X@W_aa + b_aa)
__device__ float g_T [N_ATOMS * H_P];  // X @ W_ap[0:75]   (no bias/relu)
__device__ float g_B [N_ATOMS * H_P];  // X @ W_ap[75:150] (no bias/relu)

// ---------------------------------------------------------------------------
// K1: fused atom projection  X[50000,75] @ [W_aa | W_ap_top | W_ap_bot][75,200]
// 32 atoms per block, 256 threads (200 compute). Microtile: 4 atoms x 1 col.
// ---------------------------------------------------------------------------
__global__ void k_proj(const float* __restrict__ X,
                       const float* __restrict__ W_aa, const float* __restrict__ b_aa,
                       const float* __restrict__ W_ap)
{
    const int TILE = 32;
    extern __shared__ float sm[];
    float* Ws = sm;               // 75*200 = 15000
    float* Xt = Ws + 75 * 200;    // 75*36  = 2700 (transposed, padded row 36)
    float* bs = Xt + 75 * 36;     // 100
    const int t  = threadIdx.x;
    const int a0 = blockIdx.x * TILE;

    for (int e = t; e < 75 * 200; e += 256) {
        int k = e / 200, c = e % 200;
        float w;
        if      (c < 100) w = W_aa[k * 100 + c];
        else if (c < 150) w = W_ap[k * 50 + (c - 100)];
        else              w = W_ap[(75 + k) * 50 + (c - 150)];
        Ws[e] = w;
    }
    for (int e = t; e < 100; e += 256) bs[e] = b_aa[e];
    for (int e = t; e < TILE * 75; e += 256) {
        int a = e / 75, k = e % 75;
        Xt[k * 36 + a] = (a0 + a < N_ATOMS) ? X[(a0 + a) * 75 + k] : 0.f;
    }
    __syncthreads();

    if (t < 200) {
        const int c = t;
        for (int ag = 0; ag < 8; ag++) {
            float acc0 = 0.f, acc1 = 0.f, acc2 = 0.f, acc3 = 0.f;
            #pragma unroll 5
            for (int k = 0; k < 75; k++) {
                float4 x = ((const float4*)(Xt + k * 36))[ag];
                float  w = Ws[k * 200 + c];
                acc0 += x.x * w; acc1 += x.y * w; acc2 += x.z * w; acc3 += x.w * w;
            }
            float r[4] = {acc0, acc1, acc2, acc3};
            #pragma unroll
            for (int rr = 0; rr < 4; rr++) {
                int a = a0 + ag * 4 + rr;
                if (a < N_ATOMS) {
                    if      (c < 100) g_AA[a * 100 + c]        = fmaxf(r[rr] + bs[c], 0.f);
                    else if (c < 150) g_T [a * 50 + (c - 100)] = r[rr];
                    else              g_B [a * 50 + (c - 150)] = r[rr];
                }
            }
        }
    }
}

// ---------------------------------------------------------------------------
// K2: atom final. Per atom: segment-sum of relu(pf@W_pa + b_pa) over its
// sorted pair range (binary search, no atomics), concat with AA, then
// relu([AA,PA] @ W_ao + b_ao). 32 atoms/block, 256 threads.
// ---------------------------------------------------------------------------
__global__ void k_atom(const float* __restrict__ PF, const int* __restrict__ pair_split,
                       const float* __restrict__ W_pa, const float* __restrict__ b_pa,
                       const float* __restrict__ W_ao, const float* __restrict__ b_ao,
                       float* __restrict__ outA)
{
    const int TILE = 32;
    extern __shared__ float sm[];
    float* Wao = sm;               // 150*50 = 7500
    float* Wpa = Wao + 7500;       // 14*50  = 700
    float* Hs  = Wpa + 700;        // 150*36 = 5400 (transposed, pad 36)
    float* bpa = Hs + 5400;        // 50
    float* bao = bpa + 50;         // 50
    int*   lo_s = (int*)(bao + 50);
    int*   hi_s = lo_s + TILE;
    const int t  = threadIdx.x;
    const int a0 = blockIdx.x * TILE;

    for (int e = t; e < 7500; e += 256) Wao[e] = W_ao[e];
    for (int e = t; e < 700;  e += 256) Wpa[e] = W_pa[e];
    if (t < 50) { bpa[t] = b_pa[t]; bao[t] = b_ao[t]; }

    if (t < TILE) {
        int key = a0 + t;
        int lo = 0, hi = N_PAIRS;
        while (lo < hi) { int m = (lo + hi) >> 1; if (pair_split[m] < key) lo = m + 1; else hi = m; }
        lo_s[t] = lo;
        int lo2 = lo, hi2 = N_PAIRS;
        while (lo2 < hi2) { int m = (lo2 + hi2) >> 1; if (pair_split[m] < key + 1) lo2 = m + 1; else hi2 = m; }
        hi_s[t] = lo2;
    }
    for (int e = t; e < TILE * 100; e += 256) {
        int a = e / 100, k = e % 100;
        Hs[k * 36 + a] = (a0 + a < N_ATOMS) ? g_AA[(a0 + a) * 100 + k] : 0.f;
    }
    __syncthreads();

    // PA segment sum: 8 threads per atom, each owns channels {cg, cg+8, ...}
    {
        const int a  = t >> 3;
        const int cg = t & 7;
        const int nch = (cg < 2) ? 7 : 6;    // 50 = 2*7 + 6*6
        float acc[7] = {0.f, 0.f, 0.f, 0.f, 0.f, 0.f, 0.f};
        if (a0 + a < N_ATOMS) {
            const int plo = lo_s[a], phi = hi_s[a];
            for (int p = plo; p < phi; p++) {
                float pf[14];
                #pragma unroll
                for (int d = 0; d < 14; d++) pf[d] = PF[p * 14 + d];
                #pragma unroll
                for (int u = 0; u < 7; u++) {
                    if (u < nch) {
                        int ch = cg + u * 8;
                        float s = bpa[ch];
                        #pragma unroll
                        for (int d = 0; d < 14; d++) s += pf[d] * Wpa[d * 50 + ch];
                        acc[u] += fmaxf(s, 0.f);
                    }
                }
            }
        }
        #pragma unroll
        for (int u = 0; u < 7; u++)
            if (u < nch) Hs[(100 + cg + u * 8) * 36 + a] = acc[u];
    }
    __syncthreads();

    // GEMM [32 x 150] @ [150 x 50]; microtile 4 atoms x 2 cols
    for (int task = t; task < 200; task += 256) {
        const int rg = task & 7;
        const int cl = task >> 3;          // 0..24
        float a00 = 0.f, a01 = 0.f, a10 = 0.f, a11 = 0.f;
        float a20 = 0.f, a21 = 0.f, a30 = 0.f, a31 = 0.f;
        #pragma unroll 5
        for (int k = 0; k < 150; k++) {
            float4 h = ((const float4*)(Hs + k * 36))[rg];
            float2 w = ((const float2*)(Wao))[k * 25 + cl];
            a00 += h.x * w.x; a01 += h.x * w.y;
            a10 += h.y * w.x; a11 += h.y * w.y;
            a20 += h.z * w.x; a21 += h.z * w.y;
            a30 += h.w * w.x; a31 += h.w * w.y;
        }
        const float bx = bao[2 * cl], by = bao[2 * cl + 1];
        float2 v;
        int a;
        a = a0 + rg * 4 + 0; if (a < N_ATOMS) { v.x = fmaxf(a00 + bx, 0.f); v.y = fmaxf(a01 + by, 0.f); *(float2*)(outA + a * 50 + 2 * cl) = v; }
        a = a0 + rg * 4 + 1; if (a < N_ATOMS) { v.x = fmaxf(a10 + bx, 0.f); v.y = fmaxf(a11 + by, 0.f); *(float2*)(outA + a * 50 + 2 * cl) = v; }
        a = a0 + rg * 4 + 2; if (a < N_ATOMS) { v.x = fmaxf(a20 + bx, 0.f); v.y = fmaxf(a21 + by, 0.f); *(float2*)(outA + a * 50 + 2 * cl) = v; }
        a = a0 + rg * 4 + 3; if (a < N_ATOMS) { v.x = fmaxf(a30 + bx, 0.f); v.y = fmaxf(a31 + by, 0.f); *(float2*)(outA + a * 50 + 2 * cl) = v; }
    }
}

// ---------------------------------------------------------------------------
// K3: pair branch. s_k = relu(T[i]+B[j]+b_ap) + relu(T[j]+B[i]+b_ap),
// PP = relu(pf@W_pp + b_pp), out = relu([s,PP] @ W_po + b_po).
// 64 pairs/block, 256 threads. GEMM microtile 4 pairs x 2 cols.
// ---------------------------------------------------------------------------
__global__ void k_pair(const float* __restrict__ PF, const int* __restrict__ a2p,
                       const float* __restrict__ b_ap,
                       const float* __restrict__ W_pp, const float* __restrict__ b_pp,
                       const float* __restrict__ W_po, const float* __restrict__ b_po,
                       float* __restrict__ outP)
{
    const int TILE = 64;
    extern __shared__ float sm[];
    float* Wpo = sm;                // 100*50 = 5000
    float* Wpp = Wpo + 5000;        // 700
    float* Ht  = Wpp + 700;         // 100*68 = 6800 (transposed, pad 68)
    float* pfs = Ht + 6800;         // 64*14 = 896
    float* bap = pfs + 896;         // 50
    float* bpp = bap + 50;
    float* bpo = bpp + 50;
    int*   iis = (int*)(bpo + 50);  // 64
    int*   jjs = iis + TILE;        // 64
    const int t  = threadIdx.x;
    const int p0 = blockIdx.x * TILE;
    const int PN = min(TILE, N_PAIRS - p0);

    for (int e = t; e < 5000; e += 256) Wpo[e] = W_po[e];
    for (int e = t; e < 700;  e += 256) Wpp[e] = W_pp[e];
    if (t < 50) { bap[t] = b_ap[t]; bpp[t] = b_pp[t]; bpo[t] = b_po[t]; }
    if (t < TILE) {
        int p = (t < PN) ? (p0 + t) : p0;  // clamp: padded lanes compute garbage, never stored
        iis[t] = a2p[2 * p];
        jjs[t] = a2p[2 * p + 1];
    }
    for (int e = t; e < TILE * 14; e += 256) {
        int pr = e / 14, d = e % 14;
        int p = (pr < PN) ? (p0 + pr) : p0;
        pfs[e] = PF[p * 14 + d];
    }
    __syncthreads();

    // s-part (T/B rows are L2-resident: 20 MB total)
    for (int e = t; e < TILE * 50; e += 256) {
        int pr = e / 50, k = e % 50;
        int i = iis[pr], j = jjs[pr];
        float v = fmaxf(g_T[i * 50 + k] + g_B[j * 50 + k] + bap[k], 0.f)
                + fmaxf(g_T[j * 50 + k] + g_B[i * 50 + k] + bap[k], 0.f);
        Ht[k * 68 + pr] = v;
    }
    // PP-part
    for (int e = t; e < TILE * 50; e += 256) {
        int pr = e / 50, c = e % 50;
        float s = bpp[c];
        #pragma unroll
        for (int d = 0; d < 14; d++) s += pfs[pr * 14 + d] * Wpp[d * 50 + c];
        Ht[(50 + c) * 68 + pr] = fmaxf(s, 0.f);
    }
    __syncthreads();

    // GEMM [64 x 100] @ [100 x 50]
    for (int task = t; task < 400; task += 256) {
        const int rg = task & 15;
        const int cl = task >> 4;          // 0..24
        float a00 = 0.f, a01 = 0.f, a10 = 0.f, a11 = 0.f;
        float a20 = 0.f, a21 = 0.f, a30 = 0.f, a31 = 0.f;
        #pragma unroll 4
        for (int k = 0; k < 100; k++) {
            float4 h = ((const float4*)(Ht + k * 68))[rg];
            float2 w = ((const float2*)(Wpo))[k * 25 + cl];
            a00 += h.x * w.x; a01 += h.x * w.y;
            a10 += h.y * w.x; a11 += h.y * w.y;
            a20 += h.z * w.x; a21 += h.z * w.y;
            a30 += h.w * w.x; a31 += h.w * w.y;
        }
        const float bx = bpo[2 * cl], by = bpo[2 * cl + 1];
        float2 v;
        int pr;
        pr = rg * 4 + 0; if (pr < PN) { v.x = fmaxf(a00 + bx, 0.f); v.y = fmaxf(a01 + by, 0.f); *(float2*)(outP + (p0 + pr) * 50 + 2 * cl) = v; }
        pr = rg * 4 + 1; if (pr < PN) { v.x = fmaxf(a10 + bx, 0.f); v.y = fmaxf(a11 + by, 0.f); *(float2*)(outP + (p0 + pr) * 50 + 2 * cl) = v; }
        pr = rg * 4 + 2; if (pr < PN) { v.x = fmaxf(a20 + bx, 0.f); v.y = fmaxf(a21 + by, 0.f); *(float2*)(outP + (p0 + pr) * 50 + 2 * cl) = v; }
        pr = rg * 4 + 3; if (pr < PN) { v.x = fmaxf(a30 + bx, 0.f); v.y = fmaxf(a31 + by, 0.f); *(float2*)(outP + (p0 + pr) * 50 + 2 * cl) = v; }
    }
}

// ---------------------------------------------------------------------------
extern "C" void kernel_launch(void* const* d_in, const int* in_sizes, int n_in,
                              void* d_out, int out_size)
{
    const float* atom_features = (const float*)d_in[0];
    const float* pair_features = (const float*)d_in[1];
    const int*   pair_split    = (const int*)  d_in[2];
    const int*   atom_to_pair  = (const int*)  d_in[3];
    const float* W_aa = (const float*)d_in[4];
    const float* b_aa = (const float*)d_in[5];
    const float* W_pa = (const float*)d_in[6];
    const float* b_pa = (const float*)d_in[7];
    const float* W_ao = (const float*)d_in[8];
    const float* b_ao = (const float*)d_in[9];
    const float* W_ap = (const float*)d_in[10];
    const float* b_ap = (const float*)d_in[11];
    const float* W_pp = (const float*)d_in[12];
    const float* b_pp = (const float*)d_in[13];
    const float* W_po = (const float*)d_in[14];
    const float* b_po = (const float*)d_in[15];

    float* outA = (float*)d_out;
    float* outP = (float*)d_out + (size_t)N_ATOMS * A_OUT;

    const int SMEM1 = (75 * 200 + 75 * 36 + 100) * 4;                       // ~71.2 KB
    const int SMEM2 = (7500 + 700 + 5400 + 100) * 4 + 2 * 32 * 4;           // ~55 KB
    const int SMEM3 = (5000 + 700 + 6800 + 896 + 150) * 4 + 2 * 64 * 4;     // ~54.7 KB

    cudaFuncSetAttribute(k_proj, cudaFuncAttributeMaxDynamicSharedMemorySize, SMEM1);
    cudaFuncSetAttribute(k_atom, cudaFuncAttributeMaxDynamicSharedMemorySize, SMEM2);
    cudaFuncSetAttribute(k_pair, cudaFuncAttributeMaxDynamicSharedMemorySize, SMEM3);

    const int gridProj = (N_ATOMS + 31) / 32;    // 1563
    const int gridAtom = (N_ATOMS + 31) / 32;    // 1563
    const int gridPair = (N_PAIRS + 63) / 64;    // 7813

    k_proj<<<gridProj, 256, SMEM1>>>(atom_features, W_aa, b_aa, W_ap);
    k_atom<<<gridAtom, 256, SMEM2>>>(pair_features, pair_split, W_pa, b_pa, W_ao, b_ao, outA);
    k_pair<<<gridPair, 256, SMEM3>>>(pair_features, atom_to_pair, b_ap, W_pp, b_pp, W_po, b_po, outP);
}

// round 6
// speedup vs baseline: 1.0886x; 1.0886x over previous
#include <cuda_runtime.h>

#define N_ATOMS 50000
#define N_PAIRS 500000
#define A_IN    75
#define P_IN    14
#define H_A     100
#define H_P     50
#define A_OUT   50
#define P_OUT   50

// Scratch (__device__ globals: the sanctioned allocation-free mechanism).
__device__ float g_AA[N_ATOMS * H_A];   // relu(X@W_aa + b_aa)
__device__ float g_T [N_ATOMS * H_P];   // X @ W_ap[0:75]
__device__ float g_B [N_ATOMS * H_P];   // X @ W_ap[75:150]
__device__ float g_Wf   [75 * 200];     // fused [W_aa | W_ap_top | W_ap_bot]
__device__ float g_Wao52[150 * 52];     // W_ao padded to 52 cols
__device__ float g_Wpo52[100 * 52];     // W_po padded to 52 cols

// ---------------------------------------------------------------------------
// k_prep: build fused/padded weight layouts once (linear loads downstream).
// ---------------------------------------------------------------------------
__global__ void k_prep(const float* __restrict__ W_aa, const float* __restrict__ W_ap,
                       const float* __restrict__ W_ao, const float* __restrict__ W_po)
{
    int idx = blockIdx.x * 256 + threadIdx.x;
    if (idx < 15000) {
        int k = idx / 200, c = idx % 200;
        float w;
        if      (c < 100) w = W_aa[k * 100 + c];
        else if (c < 150) w = W_ap[k * 50 + (c - 100)];
        else              w = W_ap[(75 + k) * 50 + (c - 150)];
        g_Wf[idx] = w;
    } else if (idx < 22800) {
        int e = idx - 15000, r = e / 52, c = e % 52;
        g_Wao52[e] = (c < 50) ? W_ao[r * 50 + c] : 0.f;
    } else if (idx < 28000) {
        int e = idx - 22800, r = e / 52, c = e % 52;
        g_Wpo52[e] = (c < 50) ? W_po[r * 50 + c] : 0.f;
    }
}

// ---------------------------------------------------------------------------
// K1: X[50000,75] @ Wf[75,200].  64 atoms/block, 256 threads.
// Microtile 4 atoms x 4 cols: 2 LDS.128 per 16 FFMA.
// NOTE: T/B boundary (fused col 150) is NOT 4-aligned -> scalar stores with
// per-column branch for all cols >= 100 (group c0=148 spans T{48,49}+B{0,1}).
// ---------------------------------------------------------------------------
__global__ void __launch_bounds__(256) k_proj(const float* __restrict__ X,
                                              const float* __restrict__ b_aa)
{
    const int TILE = 64;
    extern __shared__ float sm[];
    float* Ws = sm;               // 75*200 = 15000
    float* Xt = Ws + 15000;       // 75*68  = 5100 (transposed, pad 68)
    float* bs = Xt + 5100;        // 100
    const int t  = threadIdx.x;
    const int a0 = blockIdx.x * TILE;

    for (int e = t; e < 15000 / 4; e += 256)
        ((float4*)Ws)[e] = ((const float4*)g_Wf)[e];
    if (t < 100) bs[t] = b_aa[t];
    for (int e = t; e < TILE * 75; e += 256) {
        int a = e / 75, k = e % 75;
        Xt[k * 68 + a] = (a0 + a < N_ATOMS) ? X[(a0 + a) * 75 + k] : 0.f;
    }
    __syncthreads();

    for (int task = t; task < 800; task += 256) {
        const int rg = task & 15;          // atom group (4 atoms)
        const int cl = task >> 4;          // col group (4 cols), 0..49
        float acc[4][4];
        #pragma unroll
        for (int r = 0; r < 4; r++)
            #pragma unroll
            for (int c = 0; c < 4; c++) acc[r][c] = 0.f;
        #pragma unroll 5
        for (int k = 0; k < 75; k++) {
            float4 x = ((const float4*)(Xt + k * 68))[rg];
            float4 w = ((const float4*)(Ws + k * 200))[cl];
            acc[0][0] += x.x * w.x; acc[0][1] += x.x * w.y; acc[0][2] += x.x * w.z; acc[0][3] += x.x * w.w;
            acc[1][0] += x.y * w.x; acc[1][1] += x.y * w.y; acc[1][2] += x.y * w.z; acc[1][3] += x.y * w.w;
            acc[2][0] += x.z * w.x; acc[2][1] += x.z * w.y; acc[2][2] += x.z * w.z; acc[2][3] += x.z * w.w;
            acc[3][0] += x.w * w.x; acc[3][1] += x.w * w.y; acc[3][2] += x.w * w.z; acc[3][3] += x.w * w.w;
        }
        const int c0 = 4 * cl;
        #pragma unroll
        for (int rr = 0; rr < 4; rr++) {
            int a = a0 + rg * 4 + rr;
            if (a >= N_ATOMS) continue;
            if (c0 < 100) {
                float4 v;
                v.x = fmaxf(acc[rr][0] + bs[c0 + 0], 0.f);
                v.y = fmaxf(acc[rr][1] + bs[c0 + 1], 0.f);
                v.z = fmaxf(acc[rr][2] + bs[c0 + 2], 0.f);
                v.w = fmaxf(acc[rr][3] + bs[c0 + 3], 0.f);
                *(float4*)(g_AA + a * 100 + c0) = v;      // a*100+c0 ≡ 0 mod 4
            } else {
                #pragma unroll
                for (int cc = 0; cc < 4; cc++) {
                    int col = c0 + cc;
                    if (col < 150) g_T[a * 50 + (col - 100)] = acc[rr][cc];
                    else           g_B[a * 50 + (col - 150)] = acc[rr][cc];
                }
            }
        }
    }
}

// ---------------------------------------------------------------------------
// K2: atom final. 64 atoms/block, 256 threads. Segment-sum via binary search
// (4 threads/atom, channel-strided), then [64x150]@[150x52pad] GEMM 4x4.
// ---------------------------------------------------------------------------
__global__ void __launch_bounds__(256) k_atom(const float* __restrict__ PF,
                       const int* __restrict__ pair_split,
                       const float* __restrict__ W_pa, const float* __restrict__ b_pa,
                       const float* __restrict__ b_ao,
                       float* __restrict__ outA)
{
    const int TILE = 64;
    extern __shared__ float sm[];
    float* Wao = sm;               // 150*52 = 7800
    float* Wpa = Wao + 7800;       // 700
    float* Hs  = Wpa + 700;        // 150*68 = 10200 (transposed, pad 68)
    float* bpa = Hs + 10200;       // 50
    float* bao = bpa + 50;         // 50
    int*   lo_s = (int*)(bao + 50);  // 64
    int*   hi_s = lo_s + TILE;       // 64
    const int t  = threadIdx.x;
    const int a0 = blockIdx.x * TILE;

    for (int e = t; e < 7800 / 4; e += 256)
        ((float4*)Wao)[e] = ((const float4*)g_Wao52)[e];
    for (int e = t; e < 700; e += 256) Wpa[e] = W_pa[e];
    if (t < 50) { bpa[t] = b_pa[t]; bao[t] = b_ao[t]; }

    if (t < TILE) {
        int key = a0 + t;
        int lo = 0, hi = N_PAIRS;
        while (lo < hi) { int m = (lo + hi) >> 1; if (pair_split[m] < key) lo = m + 1; else hi = m; }
        lo_s[t] = lo;
        int lo2 = lo, hi2 = N_PAIRS;
        while (lo2 < hi2) { int m = (lo2 + hi2) >> 1; if (pair_split[m] < key + 1) lo2 = m + 1; else hi2 = m; }
        hi_s[t] = lo2;
    }
    for (int e = t; e < TILE * 100; e += 256) {
        int a = e / 100, k = e % 100;
        Hs[k * 68 + a] = (a0 + a < N_ATOMS) ? g_AA[(a0 + a) * 100 + k] : 0.f;
    }
    __syncthreads();

    // PA segment sum: 4 threads/atom; thread cg owns channels {cg, cg+4, ...}
    {
        const int a  = t >> 2;
        const int cg = t & 3;
        const int nch = (cg < 2) ? 13 : 12;   // 50 = 2*13 + 2*12
        float acc[13];
        #pragma unroll
        for (int u = 0; u < 13; u++) acc[u] = 0.f;
        if (a0 + a < N_ATOMS) {
            const int plo = lo_s[a], phi = hi_s[a];
            for (int p = plo; p < phi; p++) {
                float pf[14];
                #pragma unroll
                for (int d2 = 0; d2 < 7; d2++) {
                    float2 v = *(const float2*)(PF + p * 14 + 2 * d2);
                    pf[2 * d2] = v.x; pf[2 * d2 + 1] = v.y;
                }
                #pragma unroll
                for (int u = 0; u < 13; u++) {
                    if (u < nch) {
                        int ch = cg + 4 * u;
                        float s = bpa[ch];
                        #pragma unroll
                        for (int d = 0; d < 14; d++) s += pf[d] * Wpa[d * 50 + ch];
                        acc[u] += fmaxf(s, 0.f);
                    }
                }
            }
        }
        #pragma unroll
        for (int u = 0; u < 13; u++)
            if (u < nch) Hs[(100 + cg + 4 * u) * 68 + a] = acc[u];
    }
    __syncthreads();

    // GEMM [64 x 150] @ [150 x 52]; 16 rg x 13 cl = 208 tasks, 4x4 microtile
    if (t < 208) {
        const int rg = t & 15;
        const int cl = t >> 4;             // 0..12
        float acc[4][4];
        #pragma unroll
        for (int r = 0; r < 4; r++)
            #pragma unroll
            for (int c = 0; c < 4; c++) acc[r][c] = 0.f;
        #pragma unroll 5
        for (int k = 0; k < 150; k++) {
            float4 h = ((const float4*)(Hs + k * 68))[rg];
            float4 w = ((const float4*)(Wao + k * 52))[cl];
            acc[0][0] += h.x * w.x; acc[0][1] += h.x * w.y; acc[0][2] += h.x * w.z; acc[0][3] += h.x * w.w;
            acc[1][0] += h.y * w.x; acc[1][1] += h.y * w.y; acc[1][2] += h.y * w.z; acc[1][3] += h.y * w.w;
            acc[2][0] += h.z * w.x; acc[2][1] += h.z * w.y; acc[2][2] += h.z * w.z; acc[2][3] += h.z * w.w;
            acc[3][0] += h.w * w.x; acc[3][1] += h.w * w.y; acc[3][2] += h.w * w.z; acc[3][3] += h.w * w.w;
        }
        const int c0 = 4 * cl;
        #pragma unroll
        for (int rr = 0; rr < 4; rr++) {
            int a = a0 + rg * 4 + rr;
            if (a >= N_ATOMS) continue;
            float v0 = fmaxf(acc[rr][0] + bao[c0 + 0], 0.f);
            float v1 = fmaxf(acc[rr][1] + bao[c0 + 1], 0.f);
            *(float2*)(outA + a * 50 + c0) = make_float2(v0, v1);
            if (c0 + 2 < 50) {
                float v2 = fmaxf(acc[rr][2] + bao[c0 + 2], 0.f);
                float v3 = fmaxf(acc[rr][3] + bao[c0 + 3], 0.f);
                *(float2*)(outA + a * 50 + c0 + 2) = make_float2(v2, v3);
            }
        }
    }
}

// ---------------------------------------------------------------------------
// K3: pair branch. 128 pairs/block, 256 threads.
// s_k = relu(T[i]+B[j]+b) + relu(T[j]+B[i]+b); PP = relu(pf@W_pp + b);
// out = relu([s,PP] @ W_po52) 4x4 microtile.
// ---------------------------------------------------------------------------
__global__ void __launch_bounds__(256) k_pair(const float* __restrict__ PF,
                       const int* __restrict__ a2p,
                       const float* __restrict__ b_ap,
                       const float* __restrict__ W_pp, const float* __restrict__ b_pp,
                       const float* __restrict__ b_po,
                       float* __restrict__ outP)
{
    const int TILE = 128;
    extern __shared__ float sm[];
    float* Wpo = sm;                // 100*52 = 5200
    float* Wpp = Wpo + 5200;        // 700
    float* Ht  = Wpp + 700;         // 100*132 = 13200 (transposed, pad 132)
    float* pfs = Ht + 13200;        // 128*14 = 1792
    float* bap = pfs + 1792;        // 50
    float* bpp = bap + 50;          // 50
    float* bpo = bpp + 50;          // 50
    int*   iis = (int*)(bpo + 50);  // 128
    int*   jjs = iis + TILE;        // 128
    const int t  = threadIdx.x;
    const int p0 = blockIdx.x * TILE;
    const int PN = min(TILE, N_PAIRS - p0);

    for (int e = t; e < 5200 / 4; e += 256)
        ((float4*)Wpo)[e] = ((const float4*)g_Wpo52)[e];
    for (int e = t; e < 700; e += 256) Wpp[e] = W_pp[e];
    if (t < 50) { bap[t] = b_ap[t]; bpp[t] = b_pp[t]; bpo[t] = b_po[t]; }
    if (t < TILE) {
        int p = (t < PN) ? (p0 + t) : p0;   // clamped lanes: garbage, never stored
        iis[t] = a2p[2 * p];
        jjs[t] = a2p[2 * p + 1];
    }
    for (int e = t; e < TILE * 7; e += 256) {     // pf as float2 x7
        int pr = e / 7, d2 = e % 7;
        int p = (pr < PN) ? (p0 + pr) : p0;
        float2 v = *(const float2*)(PF + p * 14 + 2 * d2);
        pfs[pr * 14 + 2 * d2] = v.x; pfs[pr * 14 + 2 * d2 + 1] = v.y;
    }
    __syncthreads();

    // s-part: float2 over L2-resident g_T/g_B (20 MB total)
    for (int e = t; e < TILE * 25; e += 256) {
        int pr = e / 25, k2 = e % 25;
        int i = iis[pr], j = jjs[pr];
        float2 ti = *(const float2*)(g_T + i * 50 + 2 * k2);
        float2 bj = *(const float2*)(g_B + j * 50 + 2 * k2);
        float2 tj = *(const float2*)(g_T + j * 50 + 2 * k2);
        float2 bi = *(const float2*)(g_B + i * 50 + 2 * k2);
        float b0 = bap[2 * k2], b1 = bap[2 * k2 + 1];
        Ht[(2 * k2)     * 132 + pr] = fmaxf(ti.x + bj.x + b0, 0.f) + fmaxf(tj.x + bi.x + b0, 0.f);
        Ht[(2 * k2 + 1) * 132 + pr] = fmaxf(ti.y + bj.y + b1, 0.f) + fmaxf(tj.y + bi.y + b1, 0.f);
    }
    // PP-part: 2 cols per pf load
    for (int e = t; e < TILE * 25; e += 256) {
        int pr = e / 25, c2 = e % 25;
        float s0 = bpp[2 * c2], s1 = bpp[2 * c2 + 1];
        #pragma unroll
        for (int d = 0; d < 14; d++) {
            float x = pfs[pr * 14 + d];
            float2 w = *(const float2*)(Wpp + d * 50 + 2 * c2);
            s0 += x * w.x; s1 += x * w.y;
        }
        Ht[(50 + 2 * c2)     * 132 + pr] = fmaxf(s0, 0.f);
        Ht[(50 + 2 * c2 + 1) * 132 + pr] = fmaxf(s1, 0.f);
    }
    __syncthreads();

    // GEMM [128 x 100] @ [100 x 52]; 32 rg x 13 cl = 416 tasks, 4x4 microtile
    for (int task = t; task < 416; task += 256) {
        const int rg = task & 31;
        const int cl = task >> 5;          // 0..12
        float acc[4][4];
        #pragma unroll
        for (int r = 0; r < 4; r++)
            #pragma unroll
            for (int c = 0; c < 4; c++) acc[r][c] = 0.f;
        #pragma unroll 4
        for (int k = 0; k < 100; k++) {
            float4 h = ((const float4*)(Ht + k * 132))[rg];
            float4 w = ((const float4*)(Wpo + k * 52))[cl];
            acc[0][0] += h.x * w.x; acc[0][1] += h.x * w.y; acc[0][2] += h.x * w.z; acc[0][3] += h.x * w.w;
            acc[1][0] += h.y * w.x; acc[1][1] += h.y * w.y; acc[1][2] += h.y * w.z; acc[1][3] += h.y * w.w;
            acc[2][0] += h.z * w.x; acc[2][1] += h.z * w.y; acc[2][2] += h.z * w.z; acc[2][3] += h.z * w.w;
            acc[3][0] += h.w * w.x; acc[3][1] += h.w * w.y; acc[3][2] += h.w * w.z; acc[3][3] += h.w * w.w;
        }
        const int c0 = 4 * cl;
        #pragma unroll
        for (int rr = 0; rr < 4; rr++) {
            int pr = rg * 4 + rr;
            if (pr >= PN) continue;
            float v0 = fmaxf(acc[rr][0] + bpo[c0 + 0], 0.f);
            float v1 = fmaxf(acc[rr][1] + bpo[c0 + 1], 0.f);
            *(float2*)(outP + (size_t)(p0 + pr) * 50 + c0) = make_float2(v0, v1);
            if (c0 + 2 < 50) {
                float v2 = fmaxf(acc[rr][2] + bpo[c0 + 2], 0.f);
                float v3 = fmaxf(acc[rr][3] + bpo[c0 + 3], 0.f);
                *(float2*)(outP + (size_t)(p0 + pr) * 50 + c0 + 2) = make_float2(v2, v3);
            }
        }
    }
}

// ---------------------------------------------------------------------------
extern "C" void kernel_launch(void* const* d_in, const int* in_sizes, int n_in,
                              void* d_out, int out_size)
{
    const float* atom_features = (const float*)d_in[0];
    const float* pair_features = (const float*)d_in[1];
    const int*   pair_split    = (const int*)  d_in[2];
    const int*   atom_to_pair  = (const int*)  d_in[3];
    const float* W_aa = (const float*)d_in[4];
    const float* b_aa = (const float*)d_in[5];
    const float* W_pa = (const float*)d_in[6];
    const float* b_pa = (const float*)d_in[7];
    const float* W_ao = (const float*)d_in[8];
    const float* b_ao = (const float*)d_in[9];
    const float* W_ap = (const float*)d_in[10];
    const float* b_ap = (const float*)d_in[11];
    const float* W_pp = (const float*)d_in[12];
    const float* b_pp = (const float*)d_in[13];
    const float* W_po = (const float*)d_in[14];
    const float* b_po = (const float*)d_in[15];

    float* outA = (float*)d_out;
    float* outP = (float*)d_out + (size_t)N_ATOMS * A_OUT;

    const int SMEM1 = (15000 + 5100 + 100) * 4;                        // 80.8 KB
    const int SMEM2 = (7800 + 700 + 10200 + 100) * 4 + 2 * 64 * 4;     // 75.7 KB
    const int SMEM3 = (5200 + 700 + 13200 + 1792 + 150) * 4 + 2 * 128 * 4; // 85.2 KB

    cudaFuncSetAttribute(k_proj, cudaFuncAttributeMaxDynamicSharedMemorySize, SMEM1);
    cudaFuncSetAttribute(k_atom, cudaFuncAttributeMaxDynamicSharedMemorySize, SMEM2);
    cudaFuncSetAttribute(k_pair, cudaFuncAttributeMaxDynamicSharedMemorySize, SMEM3);

    k_prep<<<110, 256>>>(W_aa, W_ap, W_ao, W_po);
    k_proj<<<(N_ATOMS + 63) / 64, 256, SMEM1>>>(atom_features, b_aa);
    k_atom<<<(N_ATOMS + 63) / 64, 256, SMEM2>>>(pair_features, pair_split, W_pa, b_pa, b_ao, outA);
    k_pair<<<(N_PAIRS + 127) / 128, 256, SMEM3>>>(pair_features, atom_to_pair, b_ap, W_pp, b_pp, b_po, outP);
}